// round 2
// baseline (speedup 1.0000x reference)
#include <cuda_runtime.h>

#define BB 2
#define PP 32768
#define VV 5023
#define LAT 32
#define HID 128
#define DIM_IN 110
#define PAD 36
#define NPTS (BB*PP)

// layer 4 has K=238 (110 initial + 128 skip)
// wT layout: per layer, [k][n] row-major, n=128 contiguous
// offsets: l0=0(110*128) l1=14080 l2=30464 l3=46848 l4=63232(238*128) l5=93696 l6=110080 l7=126464 end=142848
__device__ float g_wT[142848];
__device__ float g_gshift[NPTS * 3];

// ---------------------------------------------------------------------------
// Weight transpose: w[n][k] -> wT[k*128+n]
// ---------------------------------------------------------------------------
__global__ void transpose_w(const float* w0, const float* w1, const float* w2,
                            const float* w3, const float* w4, const float* w5,
                            const float* w6, const float* w7) {
    int l = blockIdx.y;
    const float* src;
    int K, off;
    switch (l) {
        case 0: src = w0; K = 110; off = 0;      break;
        case 1: src = w1; K = 128; off = 14080;  break;
        case 2: src = w2; K = 128; off = 30464;  break;
        case 3: src = w3; K = 128; off = 46848;  break;
        case 4: src = w4; K = 238; off = 63232;  break;
        case 5: src = w5; K = 128; off = 93696;  break;
        case 6: src = w6; K = 128; off = 110080; break;
        default: src = w7; K = 128; off = 126464; break;
    }
    int total = K * 128;
    for (int i = blockIdx.x * blockDim.x + threadIdx.x; i < total;
         i += gridDim.x * blockDim.x) {
        int k = i >> 7;
        int n = i & 127;
        g_wT[off + i] = src[n * K + k];
    }
}

// ---------------------------------------------------------------------------
// NN search + gshift.  Block = 256 threads, 2 points/thread (512 pts/block).
// Shared: all V verts as (x, y, z, 0.5*|v|^2).  score = 0.5|v|^2 - p.v;
// d2 = p2 + 2*score (same expansion as reference), clamped at 0.
// ---------------------------------------------------------------------------
__global__ void nn_kernel(const float* __restrict__ pts,
                          const float* __restrict__ deformed,
                          const float* __restrict__ cano) {
    extern __shared__ float4 sv[];
    const int blockBase = blockIdx.x * 512;
    const int b = blockBase / PP;
    const float* dv = deformed + (size_t)b * VV * 3;
    for (int v = threadIdx.x; v < VV; v += 256) {
        float x = dv[3 * v + 0];
        float y = dv[3 * v + 1];
        float z = dv[3 * v + 2];
        sv[v] = make_float4(x, y, z, 0.5f * (x * x + y * y + z * z));
    }
    __syncthreads();

    const int pA = blockBase + threadIdx.x;
    const int pB = pA + 256;
    float ax = pts[pA * 3 + 0], ay = pts[pA * 3 + 1], az = pts[pA * 3 + 2];
    float bx = pts[pB * 3 + 0], by = pts[pB * 3 + 1], bz = pts[pB * 3 + 2];

    float bsA = 3.4e38f, bsB = 3.4e38f;
    int iA = 0, iB = 0;
#pragma unroll 4
    for (int v = 0; v < VV; ++v) {
        float4 q = sv[v];
        float sA = fmaf(-q.x, ax, fmaf(-q.y, ay, fmaf(-q.z, az, q.w)));
        float sB = fmaf(-q.x, bx, fmaf(-q.y, by, fmaf(-q.z, bz, q.w)));
        if (sA < bsA) { bsA = sA; iA = v; }
        if (sB < bsB) { bsB = sB; iB = v; }
    }
    {
        float p2 = fmaf(ax, ax, fmaf(ay, ay, az * az));
        float dist = fmaxf(fmaf(2.f, bsA, p2), 0.f);
        float w = __expf(-dist);
        float4 q = sv[iA];
        g_gshift[pA * 3 + 0] = (cano[iA * 3 + 0] - q.x) * w;
        g_gshift[pA * 3 + 1] = (cano[iA * 3 + 1] - q.y) * w;
        g_gshift[pA * 3 + 2] = (cano[iA * 3 + 2] - q.z) * w;
    }
    {
        float p2 = fmaf(bx, bx, fmaf(by, by, bz * bz));
        float dist = fmaxf(fmaf(2.f, bsB, p2), 0.f);
        float w = __expf(-dist);
        float4 q = sv[iB];
        g_gshift[pB * 3 + 0] = (cano[iB * 3 + 0] - q.x) * w;
        g_gshift[pB * 3 + 1] = (cano[iB * 3 + 1] - q.y) * w;
        g_gshift[pB * 3 + 2] = (cano[iB * 3 + 2] - q.z) * w;
    }
}

// ---------------------------------------------------------------------------
// MLP kernel.  Block = 128 threads, tile = 32 points.
// Thread tid: ng = tid>>2 (neurons 4ng..4ng+3), tg = tid&3 (points tg*8..tg*8+7)
// acc[ni*8+tj] register tile.  Activations in smem [k][t] with stride PAD=36.
// ---------------------------------------------------------------------------
__device__ __forceinline__ void gemm_block(float acc[32], const float* xs,
                                           const float* wT, int K, int ng, int tg) {
#pragma unroll 2
    for (int k = 0; k < K; ++k) {
        float4 w = __ldg(reinterpret_cast<const float4*>(wT + (size_t)k * 128) + ng);
        float4 a = *reinterpret_cast<const float4*>(xs + k * PAD + tg * 8);
        float4 c = *reinterpret_cast<const float4*>(xs + k * PAD + tg * 8 + 4);
        float wv[4] = {w.x, w.y, w.z, w.w};
        float xv[8] = {a.x, a.y, a.z, a.w, c.x, c.y, c.z, c.w};
#pragma unroll
        for (int ni = 0; ni < 4; ++ni)
#pragma unroll
            for (int tj = 0; tj < 8; ++tj)
                acc[ni * 8 + tj] = fmaf(wv[ni], xv[tj], acc[ni * 8 + tj]);
    }
}

__device__ __forceinline__ void bias_init(float acc[32], const float* bias, int ng) {
    float4 bb = __ldg(reinterpret_cast<const float4*>(bias) + ng);
    float bv[4] = {bb.x, bb.y, bb.z, bb.w};
#pragma unroll
    for (int ni = 0; ni < 4; ++ni)
#pragma unroll
        for (int tj = 0; tj < 8; ++tj) acc[ni * 8 + tj] = bv[ni];
}

__device__ __forceinline__ void store_relu(float* xd, const float acc[32], int ng, int tg) {
#pragma unroll
    for (int ni = 0; ni < 4; ++ni) {
        float4 v0 = make_float4(fmaxf(acc[ni * 8 + 0], 0.f), fmaxf(acc[ni * 8 + 1], 0.f),
                                fmaxf(acc[ni * 8 + 2], 0.f), fmaxf(acc[ni * 8 + 3], 0.f));
        float4 v1 = make_float4(fmaxf(acc[ni * 8 + 4], 0.f), fmaxf(acc[ni * 8 + 5], 0.f),
                                fmaxf(acc[ni * 8 + 6], 0.f), fmaxf(acc[ni * 8 + 7], 0.f));
        *reinterpret_cast<float4*>(xd + (4 * ng + ni) * PAD + tg * 8) = v0;
        *reinterpret_cast<float4*>(xd + (4 * ng + ni) * PAD + tg * 8 + 4) = v1;
    }
}

__global__ void __launch_bounds__(128)
mlp_kernel(const float* __restrict__ pts, const float* __restrict__ latent,
           const float* __restrict__ b0, const float* __restrict__ b1,
           const float* __restrict__ b2, const float* __restrict__ b3,
           const float* __restrict__ b4, const float* __restrict__ b5,
           const float* __restrict__ b6, const float* __restrict__ b7,
           const float* __restrict__ w_out, const float* __restrict__ b_out,
           float* __restrict__ out) {
    extern __shared__ float sm[];
    float* initf = sm;                       // DIM_IN * PAD
    float* xs0 = sm + DIM_IN * PAD;          // HID * PAD
    float* xs1 = xs0 + HID * PAD;            // HID * PAD

    const int tid = threadIdx.x;
    const int bp0 = blockIdx.x * 32;

    // ---- build initial features (pe(pts,10) | pe(gshift,2) | latent) ----
    if (tid < 32) {
        const int t = tid;
        const int bp = bp0 + t;
        float px = pts[bp * 3 + 0], py = pts[bp * 3 + 1], pz = pts[bp * 3 + 2];
        float gx = g_gshift[bp * 3 + 0], gy = g_gshift[bp * 3 + 1], gz = g_gshift[bp * 3 + 2];
        initf[0 * PAD + t] = px;
        initf[1 * PAD + t] = py;
        initf[2 * PAD + t] = pz;
        int o = 3;
        float f = 1.f;
#pragma unroll
        for (int l = 0; l < 10; ++l) {
            float s, c;
            __sincosf(px * f, &s, &c); initf[(o + 0) * PAD + t] = s; initf[(o + 3) * PAD + t] = c;
            __sincosf(py * f, &s, &c); initf[(o + 1) * PAD + t] = s; initf[(o + 4) * PAD + t] = c;
            __sincosf(pz * f, &s, &c); initf[(o + 2) * PAD + t] = s; initf[(o + 5) * PAD + t] = c;
            o += 6;
            f *= 2.f;
        }
        initf[63 * PAD + t] = gx;
        initf[64 * PAD + t] = gy;
        initf[65 * PAD + t] = gz;
        o = 66;
        f = 1.f;
#pragma unroll
        for (int l = 0; l < 2; ++l) {
            float s, c;
            __sincosf(gx * f, &s, &c); initf[(o + 0) * PAD + t] = s; initf[(o + 3) * PAD + t] = c;
            __sincosf(gy * f, &s, &c); initf[(o + 1) * PAD + t] = s; initf[(o + 4) * PAD + t] = c;
            __sincosf(gz * f, &s, &c); initf[(o + 2) * PAD + t] = s; initf[(o + 5) * PAD + t] = c;
            o += 6;
            f *= 2.f;
        }
#pragma unroll
        for (int j = 0; j < 32; ++j) initf[(78 + j) * PAD + t] = latent[(size_t)bp * LAT + j];
    }
    __syncthreads();

    const int ng = tid >> 2;
    const int tg = tid & 3;
    float acc[32];

    // layer 0
    bias_init(acc, b0, ng);
    gemm_block(acc, initf, g_wT + 0, DIM_IN, ng, tg);
    store_relu(xs0, acc, ng, tg);
    __syncthreads();

    const float* bptr[8] = {b0, b1, b2, b3, b4, b5, b6, b7};
    const int offs[8] = {0, 14080, 30464, 46848, 63232, 93696, 110080, 126464};
    float* cur = xs0;
    float* nxt = xs1;
#pragma unroll
    for (int l = 1; l < 8; ++l) {
        bias_init(acc, bptr[l], ng);
        if (l == 4) {
            gemm_block(acc, initf, g_wT + 63232, DIM_IN, ng, tg);
            gemm_block(acc, cur, g_wT + 63232 + DIM_IN * HID, HID, ng, tg);
        } else {
            gemm_block(acc, cur, g_wT + offs[l], HID, ng, tg);
        }
        if (l == 7) {
            // last_feat = pre-activation of layer 7
            float* out2 = out + (size_t)NPTS * 3;
#pragma unroll
            for (int ni = 0; ni < 4; ++ni)
#pragma unroll
                for (int tj = 0; tj < 8; ++tj)
                    out2[(size_t)(bp0 + tg * 8 + tj) * HID + (4 * ng + ni)] = acc[ni * 8 + tj];
        }
        store_relu(nxt, acc, ng, tg);
        __syncthreads();
        float* tmp = cur; cur = nxt; nxt = tmp;
    }

    // ---- output head: mlp_shift = relu(x7) @ w_out.T + b_out ----
    if (tid < 96) {
        const int t = tid & 31;
        const int c = tid >> 5;  // 0..2
        float s = __ldg(b_out + c);
        const float* wrow = w_out + c * HID;
#pragma unroll 4
        for (int n = 0; n < HID; ++n) s = fmaf(cur[n * PAD + t], __ldg(wrow + n), s);
        const int bp = bp0 + t;
        out[bp * 3 + c] = pts[bp * 3 + c] + g_gshift[bp * 3 + c] + s;
    }
}

// ---------------------------------------------------------------------------
extern "C" void kernel_launch(void* const* d_in, const int* in_sizes, int n_in,
                              void* d_out, int out_size) {
    const float* pts      = (const float*)d_in[0];
    const float* deformed = (const float*)d_in[1];
    const float* cano     = (const float*)d_in[2];
    const float* latent   = (const float*)d_in[3];
    const float* w[8];
    const float* b[8];
    for (int i = 0; i < 8; ++i) {
        w[i] = (const float*)d_in[4 + 2 * i];
        b[i] = (const float*)d_in[5 + 2 * i];
    }
    const float* w_out = (const float*)d_in[20];
    const float* b_out = (const float*)d_in[21];
    float* out = (float*)d_out;

    const int smem_nn = VV * 16;  // 80368 B
    const int smem_mlp = (DIM_IN * PAD + 2 * HID * PAD) * 4;  // 52704 B
    cudaFuncSetAttribute(nn_kernel, cudaFuncAttributeMaxDynamicSharedMemorySize, smem_nn);
    cudaFuncSetAttribute(mlp_kernel, cudaFuncAttributeMaxDynamicSharedMemorySize, smem_mlp);

    transpose_w<<<dim3(120, 8), 256>>>(w[0], w[1], w[2], w[3], w[4], w[5], w[6], w[7]);
    nn_kernel<<<NPTS / 512, 256, smem_nn>>>(pts, deformed, cano);
    mlp_kernel<<<NPTS / 32, 128, smem_mlp>>>(pts, latent, b[0], b[1], b[2], b[3], b[4],
                                             b[5], b[6], b[7], w_out, b_out, out);
}

// round 5
// speedup vs baseline: 1.1124x; 1.1124x over previous
#include <cuda_runtime.h>

#define BB 2
#define PP 32768
#define VV 5023
#define LAT 32
#define HID 128
#define DIM_IN 110
#define PAD 36
#define NPTS (BB*PP)

// layer 4 has K=238 (110 initial + 128 skip)
// wT layout: per layer, [k][n] row-major, n=128 contiguous
__device__ float g_wT[142848];
__device__ float g_gshift[NPTS * 3];

// ---------------------------------------------------------------------------
// packed f32x2 helpers (FFMA2 path — 2 fp32 MACs per lane per instruction)
// ---------------------------------------------------------------------------
typedef unsigned long long u64t;

__device__ __forceinline__ u64t pack2(float lo, float hi) {
    u64t r;
    asm("mov.b64 %0,{%1,%2};" : "=l"(r) : "f"(lo), "f"(hi));
    return r;
}
__device__ __forceinline__ void unpack2(u64t v, float& lo, float& hi) {
    asm("mov.b64 {%0,%1},%2;" : "=f"(lo), "=f"(hi) : "l"(v));
}
__device__ __forceinline__ void ffma2(u64t& acc, u64t x, u64t w) {
    asm("fma.rn.f32x2 %0,%1,%2,%0;" : "+l"(acc) : "l"(x), "l"(w));
}

// ---------------------------------------------------------------------------
// Weight transpose: w[n][k] -> wT[k*128+n]
// ---------------------------------------------------------------------------
__global__ void transpose_w(const float* w0, const float* w1, const float* w2,
                            const float* w3, const float* w4, const float* w5,
                            const float* w6, const float* w7) {
    int l = blockIdx.y;
    const float* src;
    int K, off;
    switch (l) {
        case 0: src = w0; K = 110; off = 0;      break;
        case 1: src = w1; K = 128; off = 14080;  break;
        case 2: src = w2; K = 128; off = 30464;  break;
        case 3: src = w3; K = 128; off = 46848;  break;
        case 4: src = w4; K = 238; off = 63232;  break;
        case 5: src = w5; K = 128; off = 93696;  break;
        case 6: src = w6; K = 128; off = 110080; break;
        default: src = w7; K = 128; off = 126464; break;
    }
    int total = K * 128;
    for (int i = blockIdx.x * blockDim.x + threadIdx.x; i < total;
         i += gridDim.x * blockDim.x) {
        int k = i >> 7;
        int n = i & 127;
        g_wT[off + i] = src[n * K + k];
    }
}

// ---------------------------------------------------------------------------
// NN search + gshift.  Block = 256 threads, 2 points/thread (512 pts/block).
// ---------------------------------------------------------------------------
__global__ void nn_kernel(const float* __restrict__ pts,
                          const float* __restrict__ deformed,
                          const float* __restrict__ cano) {
    extern __shared__ float4 sv[];
    const int blockBase = blockIdx.x * 512;
    const int b = blockBase / PP;
    const float* dv = deformed + (size_t)b * VV * 3;
    for (int v = threadIdx.x; v < VV; v += 256) {
        float x = dv[3 * v + 0];
        float y = dv[3 * v + 1];
        float z = dv[3 * v + 2];
        sv[v] = make_float4(x, y, z, 0.5f * (x * x + y * y + z * z));
    }
    __syncthreads();

    const int pA = blockBase + threadIdx.x;
    const int pB = pA + 256;
    float ax = pts[pA * 3 + 0], ay = pts[pA * 3 + 1], az = pts[pA * 3 + 2];
    float bx = pts[pB * 3 + 0], by = pts[pB * 3 + 1], bz = pts[pB * 3 + 2];

    float bsA = 3.4e38f, bsB = 3.4e38f;
    int iA = 0, iB = 0;
#pragma unroll 4
    for (int v = 0; v < VV; ++v) {
        float4 q = sv[v];
        float sA = fmaf(-q.x, ax, fmaf(-q.y, ay, fmaf(-q.z, az, q.w)));
        float sB = fmaf(-q.x, bx, fmaf(-q.y, by, fmaf(-q.z, bz, q.w)));
        if (sA < bsA) { bsA = sA; iA = v; }
        if (sB < bsB) { bsB = sB; iB = v; }
    }
    {
        float p2 = fmaf(ax, ax, fmaf(ay, ay, az * az));
        float dist = fmaxf(fmaf(2.f, bsA, p2), 0.f);
        float w = __expf(-dist);
        float4 q = sv[iA];
        g_gshift[pA * 3 + 0] = (cano[iA * 3 + 0] - q.x) * w;
        g_gshift[pA * 3 + 1] = (cano[iA * 3 + 1] - q.y) * w;
        g_gshift[pA * 3 + 2] = (cano[iA * 3 + 2] - q.z) * w;
    }
    {
        float p2 = fmaf(bx, bx, fmaf(by, by, bz * bz));
        float dist = fmaxf(fmaf(2.f, bsB, p2), 0.f);
        float w = __expf(-dist);
        float4 q = sv[iB];
        g_gshift[pB * 3 + 0] = (cano[iB * 3 + 0] - q.x) * w;
        g_gshift[pB * 3 + 1] = (cano[iB * 3 + 1] - q.y) * w;
        g_gshift[pB * 3 + 2] = (cano[iB * 3 + 2] - q.z) * w;
    }
}

// ---------------------------------------------------------------------------
// MLP kernel (FFMA2).  Block = 128 threads, tile = 32 points.
// Thread tid: ng = tid>>2 (neurons 4ng..4ng+3), tg = tid&3 (points tg*8..tg*8+7)
// acc2[ni*4+tp] holds f32x2 pair = points (tg*8+2tp, tg*8+2tp+1), neuron 4ng+ni.
// ---------------------------------------------------------------------------
__device__ __forceinline__ void gemm_block2(u64t acc[16], const float* xs,
                                            const float* wT, int K, int ng, int tg) {
#pragma unroll 2
    for (int k = 0; k < K; ++k) {
        float4 w = __ldg(reinterpret_cast<const float4*>(wT + (size_t)k * 128) + ng);
        const ulonglong2* xp = reinterpret_cast<const ulonglong2*>(xs + k * PAD + tg * 8);
        ulonglong2 A = xp[0];
        ulonglong2 B = xp[1];
        u64t xv[4] = {A.x, A.y, B.x, B.y};
        u64t wp[4] = {pack2(w.x, w.x), pack2(w.y, w.y), pack2(w.z, w.z), pack2(w.w, w.w)};
#pragma unroll
        for (int ni = 0; ni < 4; ++ni)
#pragma unroll
            for (int tp = 0; tp < 4; ++tp)
                ffma2(acc[ni * 4 + tp], xv[tp], wp[ni]);
    }
}

__device__ __forceinline__ void bias_init2(u64t acc[16], const float* bias, int ng) {
    float4 bb = __ldg(reinterpret_cast<const float4*>(bias) + ng);
    float bv[4] = {bb.x, bb.y, bb.z, bb.w};
#pragma unroll
    for (int ni = 0; ni < 4; ++ni) {
        u64t p = pack2(bv[ni], bv[ni]);
#pragma unroll
        for (int tp = 0; tp < 4; ++tp) acc[ni * 4 + tp] = p;
    }
}

__device__ __forceinline__ void store_relu2(float* xd, const u64t acc[16], int ng, int tg) {
#pragma unroll
    for (int ni = 0; ni < 4; ++ni) {
        float v[8];
#pragma unroll
        for (int tp = 0; tp < 4; ++tp) unpack2(acc[ni * 4 + tp], v[2 * tp], v[2 * tp + 1]);
        float4 v0 = make_float4(fmaxf(v[0], 0.f), fmaxf(v[1], 0.f), fmaxf(v[2], 0.f), fmaxf(v[3], 0.f));
        float4 v1 = make_float4(fmaxf(v[4], 0.f), fmaxf(v[5], 0.f), fmaxf(v[6], 0.f), fmaxf(v[7], 0.f));
        *reinterpret_cast<float4*>(xd + (4 * ng + ni) * PAD + tg * 8) = v0;
        *reinterpret_cast<float4*>(xd + (4 * ng + ni) * PAD + tg * 8 + 4) = v1;
    }
}

__global__ void __launch_bounds__(128)
mlp_kernel(const float* __restrict__ pts, const float* __restrict__ latent,
           const float* __restrict__ b0, const float* __restrict__ b1,
           const float* __restrict__ b2, const float* __restrict__ b3,
           const float* __restrict__ b4, const float* __restrict__ b5,
           const float* __restrict__ b6, const float* __restrict__ b7,
           const float* __restrict__ w_out, const float* __restrict__ b_out,
           float* __restrict__ out) {
    extern __shared__ float sm[];
    float* initf = sm;                       // DIM_IN * PAD
    float* xs0 = sm + DIM_IN * PAD;          // HID * PAD
    float* xs1 = xs0 + HID * PAD;            // HID * PAD

    const int tid = threadIdx.x;
    const int bp0 = blockIdx.x * 32;

    // ---- build initial features (pe(pts,10) | pe(gshift,2) | latent) ----
    if (tid < 32) {
        const int t = tid;
        const int bp = bp0 + t;
        float px = pts[bp * 3 + 0], py = pts[bp * 3 + 1], pz = pts[bp * 3 + 2];
        float gx = g_gshift[bp * 3 + 0], gy = g_gshift[bp * 3 + 1], gz = g_gshift[bp * 3 + 2];
        initf[0 * PAD + t] = px;
        initf[1 * PAD + t] = py;
        initf[2 * PAD + t] = pz;
        int o = 3;
        float f = 1.f;
#pragma unroll
        for (int l = 0; l < 10; ++l) {
            float s, c;
            __sincosf(px * f, &s, &c); initf[(o + 0) * PAD + t] = s; initf[(o + 3) * PAD + t] = c;
            __sincosf(py * f, &s, &c); initf[(o + 1) * PAD + t] = s; initf[(o + 4) * PAD + t] = c;
            __sincosf(pz * f, &s, &c); initf[(o + 2) * PAD + t] = s; initf[(o + 5) * PAD + t] = c;
            o += 6;
            f *= 2.f;
        }
        initf[63 * PAD + t] = gx;
        initf[64 * PAD + t] = gy;
        initf[65 * PAD + t] = gz;
        o = 66;
        f = 1.f;
#pragma unroll
        for (int l = 0; l < 2; ++l) {
            float s, c;
            __sincosf(gx * f, &s, &c); initf[(o + 0) * PAD + t] = s; initf[(o + 3) * PAD + t] = c;
            __sincosf(gy * f, &s, &c); initf[(o + 1) * PAD + t] = s; initf[(o + 4) * PAD + t] = c;
            __sincosf(gz * f, &s, &c); initf[(o + 2) * PAD + t] = s; initf[(o + 5) * PAD + t] = c;
            o += 6;
            f *= 2.f;
        }
#pragma unroll
        for (int j = 0; j < 32; ++j) initf[(78 + j) * PAD + t] = latent[(size_t)bp * LAT + j];
    }
    __syncthreads();

    const int ng = tid >> 2;
    const int tg = tid & 3;
    u64t acc[16];

    // layer 0
    bias_init2(acc, b0, ng);
    gemm_block2(acc, initf, g_wT + 0, DIM_IN, ng, tg);
    store_relu2(xs0, acc, ng, tg);
    __syncthreads();

    const float* bptr[8] = {b0, b1, b2, b3, b4, b5, b6, b7};
    const int offs[8] = {0, 14080, 30464, 46848, 63232, 93696, 110080, 126464};
    float* cur = xs0;
    float* nxt = xs1;
#pragma unroll
    for (int l = 1; l < 8; ++l) {
        bias_init2(acc, bptr[l], ng);
        if (l == 4) {
            gemm_block2(acc, initf, g_wT + 63232, DIM_IN, ng, tg);
            gemm_block2(acc, cur, g_wT + 63232 + DIM_IN * HID, HID, ng, tg);
        } else {
            gemm_block2(acc, cur, g_wT + offs[l], HID, ng, tg);
        }
        if (l == 7) {
            // last_feat = pre-activation of layer 7
            float* out2 = out + (size_t)NPTS * 3;
#pragma unroll
            for (int ni = 0; ni < 4; ++ni)
#pragma unroll
                for (int tp = 0; tp < 4; ++tp) {
                    float lo, hi;
                    unpack2(acc[ni * 4 + tp], lo, hi);
                    out2[(size_t)(bp0 + tg * 8 + 2 * tp) * HID + (4 * ng + ni)] = lo;
                    out2[(size_t)(bp0 + tg * 8 + 2 * tp + 1) * HID + (4 * ng + ni)] = hi;
                }
        }
        store_relu2(nxt, acc, ng, tg);
        __syncthreads();
        float* tmp = cur; cur = nxt; nxt = tmp;
    }

    // ---- output head: mlp_shift = relu(x7) @ w_out.T + b_out ----
    if (tid < 96) {
        const int t = tid & 31;
        const int c = tid >> 5;  // 0..2
        float s = __ldg(b_out + c);
        const float* wrow = w_out + c * HID;
#pragma unroll 4
        for (int n = 0; n < HID; ++n) s = fmaf(cur[n * PAD + t], __ldg(wrow + n), s);
        const int bp = bp0 + t;
        out[bp * 3 + c] = pts[bp * 3 + c] + g_gshift[bp * 3 + c] + s;
    }
}

// ---------------------------------------------------------------------------
extern "C" void kernel_launch(void* const* d_in, const int* in_sizes, int n_in,
                              void* d_out, int out_size) {
    const float* pts      = (const float*)d_in[0];
    const float* deformed = (const float*)d_in[1];
    const float* cano     = (const float*)d_in[2];
    const float* latent   = (const float*)d_in[3];
    const float* w[8];
    const float* b[8];
    for (int i = 0; i < 8; ++i) {
        w[i] = (const float*)d_in[4 + 2 * i];
        b[i] = (const float*)d_in[5 + 2 * i];
    }
    const float* w_out = (const float*)d_in[20];
    const float* b_out = (const float*)d_in[21];
    float* out = (float*)d_out;

    const int smem_nn = VV * 16;  // 80368 B
    const int smem_mlp = (DIM_IN * PAD + 2 * HID * PAD) * 4;  // 52704 B
    cudaFuncSetAttribute(nn_kernel, cudaFuncAttributeMaxDynamicSharedMemorySize, smem_nn);
    cudaFuncSetAttribute(mlp_kernel, cudaFuncAttributeMaxDynamicSharedMemorySize, smem_mlp);

    transpose_w<<<dim3(120, 8), 256>>>(w[0], w[1], w[2], w[3], w[4], w[5], w[6], w[7]);
    nn_kernel<<<NPTS / 512, 256, smem_nn>>>(pts, deformed, cano);
    mlp_kernel<<<NPTS / 32, 128, smem_mlp>>>(pts, latent, b[0], b[1], b[2], b[3], b[4],
                                             b[5], b[6], b[7], w_out, b_out, out);
}

// round 7
// speedup vs baseline: 2.5178x; 2.2634x over previous
#include <cuda_runtime.h>
#include <cuda_bf16.h>
#include <cstdint>

#define BB 2
#define PP 32768
#define VV 5023
#define LAT 32
#define HID 128
#define NPTS (BB*PP)
#define NSUB 9
#define STRIDE 136          // bf16 units per activation row (272B, 17*16B -> conflict-free ldmatrix)
#define ROWB 272

// Weight fragments in mma B-register layout:
// index [(s*2+h)*8 + ks][nt][lane] as uint2 (b0,b1)
__device__ uint2 g_wfrag[NSUB * 2 * 8 * 16 * 32];
__device__ float g_gshift[NPTS * 3];

// ---------------------------------------------------------------------------
// sub-layer table: (source weight, Ktot, k0, valid)
// s: 0..3 = w0..w3, 4 = w4 init-part (cols 0..109), 5 = w4 hidden-part (cols 110..237),
//    6..8 = w5..w7
// ---------------------------------------------------------------------------

__global__ void prep_wfrag(const float* w0, const float* w1, const float* w2,
                           const float* w3, const float* w4, const float* w5,
                           const float* w6, const float* w7) {
    int idx = blockIdx.x * blockDim.x + threadIdx.x;
    if (idx >= NSUB * 2 * 8 * 16 * 32) return;
    int lane = idx & 31;
    int nt = (idx >> 5) & 15;
    int ks = (idx >> 9) & 7;
    int h  = (idx >> 12) & 1;
    int s  = idx >> 13;

    const float* w; int Ktot, k0, valid;
    switch (s) {
        case 0: w = w0; Ktot = 110; k0 = 0;   valid = 110; break;
        case 1: w = w1; Ktot = 128; k0 = 0;   valid = 128; break;
        case 2: w = w2; Ktot = 128; k0 = 0;   valid = 128; break;
        case 3: w = w3; Ktot = 128; k0 = 0;   valid = 128; break;
        case 4: w = w4; Ktot = 238; k0 = 0;   valid = 110; break;
        case 5: w = w4; Ktot = 238; k0 = 110; valid = 128; break;
        case 6: w = w5; Ktot = 128; k0 = 0;   valid = 128; break;
        case 7: w = w6; Ktot = 128; k0 = 0;   valid = 128; break;
        default: w = w7; Ktot = 128; k0 = 0;  valid = 128; break;
    }
    int n = nt * 8 + (lane >> 2);
    int kb = ks * 16 + (lane & 3) * 2;
    unsigned short v16[4];
#pragma unroll
    for (int j = 0; j < 4; ++j) {
        int kk = kb + (j & 1) + (j >> 1) * 8;
        float v = (kk < valid) ? w[n * Ktot + k0 + kk] : 0.f;
        __nv_bfloat16 hi = __float2bfloat16_rn(v);
        __nv_bfloat16 r = (h == 0) ? hi : __float2bfloat16_rn(v - __bfloat162float(hi));
        v16[j] = __bfloat16_as_ushort(r);
    }
    uint2 out;
    out.x = (uint32_t)v16[0] | ((uint32_t)v16[1] << 16);
    out.y = (uint32_t)v16[2] | ((uint32_t)v16[3] << 16);
    g_wfrag[idx] = out;
}

// ---------------------------------------------------------------------------
// NN search + gshift (unchanged)
// ---------------------------------------------------------------------------
__global__ void nn_kernel(const float* __restrict__ pts,
                          const float* __restrict__ deformed,
                          const float* __restrict__ cano) {
    extern __shared__ float4 sv[];
    const int blockBase = blockIdx.x * 512;
    const int b = blockBase / PP;
    const float* dv = deformed + (size_t)b * VV * 3;
    for (int v = threadIdx.x; v < VV; v += 256) {
        float x = dv[3 * v + 0], y = dv[3 * v + 1], z = dv[3 * v + 2];
        sv[v] = make_float4(x, y, z, 0.5f * (x * x + y * y + z * z));
    }
    __syncthreads();
    const int pA = blockBase + threadIdx.x;
    const int pB = pA + 256;
    float ax = pts[pA * 3 + 0], ay = pts[pA * 3 + 1], az = pts[pA * 3 + 2];
    float bx = pts[pB * 3 + 0], by = pts[pB * 3 + 1], bz = pts[pB * 3 + 2];
    float bsA = 3.4e38f, bsB = 3.4e38f;
    int iA = 0, iB = 0;
#pragma unroll 4
    for (int v = 0; v < VV; ++v) {
        float4 q = sv[v];
        float sA = fmaf(-q.x, ax, fmaf(-q.y, ay, fmaf(-q.z, az, q.w)));
        float sB = fmaf(-q.x, bx, fmaf(-q.y, by, fmaf(-q.z, bz, q.w)));
        if (sA < bsA) { bsA = sA; iA = v; }
        if (sB < bsB) { bsB = sB; iB = v; }
    }
    {
        float p2 = fmaf(ax, ax, fmaf(ay, ay, az * az));
        float w = __expf(-fmaxf(fmaf(2.f, bsA, p2), 0.f));
        float4 q = sv[iA];
        g_gshift[pA * 3 + 0] = (cano[iA * 3 + 0] - q.x) * w;
        g_gshift[pA * 3 + 1] = (cano[iA * 3 + 1] - q.y) * w;
        g_gshift[pA * 3 + 2] = (cano[iA * 3 + 2] - q.z) * w;
    }
    {
        float p2 = fmaf(bx, bx, fmaf(by, by, bz * bz));
        float w = __expf(-fmaxf(fmaf(2.f, bsB, p2), 0.f));
        float4 q = sv[iB];
        g_gshift[pB * 3 + 0] = (cano[iB * 3 + 0] - q.x) * w;
        g_gshift[pB * 3 + 1] = (cano[iB * 3 + 1] - q.y) * w;
        g_gshift[pB * 3 + 2] = (cano[iB * 3 + 2] - q.z) * w;
    }
}

// ---------------------------------------------------------------------------
// MMA helpers
// ---------------------------------------------------------------------------
__device__ __forceinline__ uint32_t smem_u32(const void* p) {
    uint32_t a;
    asm("{ .reg .u64 t; cvta.to.shared.u64 t, %1; cvt.u32.u64 %0, t; }" : "=r"(a) : "l"(p));
    return a;
}

__device__ __forceinline__ void ldmA(uint32_t a[4], uint32_t su, int rowbase, int kbase, int lane) {
    int grp = lane >> 3, ri = lane & 7;
    int row = rowbase + ri + ((grp & 1) << 3);
    int col = kbase + ((grp & 2) << 2);
    uint32_t addr = su + (uint32_t)(row * ROWB + col * 2);
    asm volatile("ldmatrix.sync.aligned.m8n8.x4.shared.b16 {%0,%1,%2,%3}, [%4];"
                 : "=r"(a[0]), "=r"(a[1]), "=r"(a[2]), "=r"(a[3]) : "r"(addr));
}

__device__ __forceinline__ void mma16816(float c[4], const uint32_t a[4], uint2 b) {
    asm volatile(
        "mma.sync.aligned.m16n8k16.row.col.f32.bf16.bf16.f32 "
        "{%0,%1,%2,%3},{%4,%5,%6,%7},{%8,%9},{%0,%1,%2,%3};"
        : "+f"(c[0]), "+f"(c[1]), "+f"(c[2]), "+f"(c[3])
        : "r"(a[0]), "r"(a[1]), "r"(a[2]), "r"(a[3]), "r"(b.x), "r"(b.y));
}

// ---------------------------------------------------------------------------
// Feature build: compute the 110-dim input feature (+18 zero pad) for one
// point and stream it into the hi/lo activation buffers (scalar bf16 stores).
// ---------------------------------------------------------------------------
__device__ __forceinline__ void put_feat(__nv_bfloat16* aH, __nv_bfloat16* aL, int col, float v) {
    __nv_bfloat16 h = __float2bfloat16_rn(v);
    aH[col] = h;
    aL[col] = __float2bfloat16_rn(v - __bfloat162float(h));
}

__device__ void build_feat(char* actH, char* actL, int row, int bp,
                           const float* __restrict__ pts, const float* __restrict__ latent) {
    __nv_bfloat16* aH = (__nv_bfloat16*)(actH + row * ROWB);
    __nv_bfloat16* aL = (__nv_bfloat16*)(actL + row * ROWB);
    float px = pts[bp * 3 + 0], py = pts[bp * 3 + 1], pz = pts[bp * 3 + 2];
    float gx = g_gshift[bp * 3 + 0], gy = g_gshift[bp * 3 + 1], gz = g_gshift[bp * 3 + 2];
    put_feat(aH, aL, 0, px); put_feat(aH, aL, 1, py); put_feat(aH, aL, 2, pz);
#pragma unroll
    for (int l = 0; l < 10; ++l) {
        float f = (float)(1 << l);
        float s, c;
        __sincosf(px * f, &s, &c); put_feat(aH, aL, 3 + 6 * l + 0, s); put_feat(aH, aL, 3 + 6 * l + 3, c);
        __sincosf(py * f, &s, &c); put_feat(aH, aL, 3 + 6 * l + 1, s); put_feat(aH, aL, 3 + 6 * l + 4, c);
        __sincosf(pz * f, &s, &c); put_feat(aH, aL, 3 + 6 * l + 2, s); put_feat(aH, aL, 3 + 6 * l + 5, c);
    }
    put_feat(aH, aL, 63, gx); put_feat(aH, aL, 64, gy); put_feat(aH, aL, 65, gz);
#pragma unroll
    for (int l = 0; l < 2; ++l) {
        float f = (float)(1 << l);
        float s, c;
        __sincosf(gx * f, &s, &c); put_feat(aH, aL, 66 + 6 * l + 0, s); put_feat(aH, aL, 66 + 6 * l + 3, c);
        __sincosf(gy * f, &s, &c); put_feat(aH, aL, 66 + 6 * l + 1, s); put_feat(aH, aL, 66 + 6 * l + 4, c);
        __sincosf(gz * f, &s, &c); put_feat(aH, aL, 66 + 6 * l + 2, s); put_feat(aH, aL, 66 + 6 * l + 5, c);
    }
#pragma unroll
    for (int j = 0; j < 32; ++j) put_feat(aH, aL, 78 + j, latent[(size_t)bp * LAT + j]);
    __nv_bfloat16 z = __float2bfloat16_rn(0.f);
#pragma unroll
    for (int j = 110; j < 128; ++j) { aH[j] = z; aL[j] = z; }
}

// ---------------------------------------------------------------------------
// SMEM layout for MLP kernel
// ---------------------------------------------------------------------------
#define OFF_AH   0
#define OFF_AL   34816
#define OFF_W    69632
#define OFF_BIAS 102400
#define OFF_WOUT 106496
#define OFF_BOUT 108032
#define SMEM_MLP 108048

__global__ void __launch_bounds__(128)
mlp_mma_kernel(const float* __restrict__ pts, const float* __restrict__ latent,
               const float* __restrict__ b0, const float* __restrict__ b1,
               const float* __restrict__ b2, const float* __restrict__ b3,
               const float* __restrict__ b4, const float* __restrict__ b5,
               const float* __restrict__ b6, const float* __restrict__ b7,
               const float* __restrict__ w_out, const float* __restrict__ b_out,
               float* __restrict__ out) {
    extern __shared__ char sm[];
    char* actH = sm + OFF_AH;
    char* actL = sm + OFF_AL;
    uint2* wst = (uint2*)(sm + OFF_W);
    float* sbias = (float*)(sm + OFF_BIAS);
    float* swout = (float*)(sm + OFF_WOUT);
    float* sbout = (float*)(sm + OFF_BOUT);

    const int tid = threadIdx.x;
    const int wid = tid >> 5;
    const int lane = tid & 31;
    const int bp0 = blockIdx.x * 128;
    const int bp = bp0 + tid;
    const uint32_t suH = smem_u32(actH);
    const uint32_t suL = smem_u32(actL);
    const int mrow = wid * 32;  // this warp's point-row base

    // stage biases / head weights
    {
        const float* bs[8] = {b0, b1, b2, b3, b4, b5, b6, b7};
        for (int i = tid; i < 1024; i += 128) sbias[i] = bs[i >> 7][i & 127];
        for (int i = tid; i < 384; i += 128) swout[i] = w_out[i];
        if (tid < 3) sbout[tid] = b_out[tid];
    }

    // build initial features (row = tid, warp-private rows)
    build_feat(actH, actL, tid, bp, pts, latent);
    __syncthreads();  // also covers bias staging

    float c[2][16][4];

    const int subOf[8] = {0, 1, 2, 3, 5, 6, 7, 8};  // layer -> primary sub (l4 uses hidden part first)

#pragma unroll 1
    for (int l = 0; l < 8; ++l) {
        // zero accumulators
#pragma unroll
        for (int mt = 0; mt < 2; ++mt)
#pragma unroll
            for (int nt = 0; nt < 16; ++nt)
#pragma unroll
                for (int j = 0; j < 4; ++j) c[mt][nt][j] = 0.f;

        const int nparts = (l == 4) ? 2 : 1;
#pragma unroll 1
        for (int part = 0; part < nparts; ++part) {
            const int s = (l == 4 && part == 1) ? 4 : subOf[l];
            if (l == 4 && part == 1) {
                // rebuild initial features into the activation buffer (skip input)
                __syncwarp();
                build_feat(actH, actL, tid, bp, pts, latent);
                __syncwarp();
            }
            const uint2* srcH = g_wfrag + (size_t)(s * 2 + 0) * 4096;
            const uint2* srcL = g_wfrag + (size_t)(s * 2 + 1) * 4096;

            // ---- stage W-hi, run products Ah*Bh and Al*Bh ----
            __syncthreads();
            {
                const uint4* s4 = (const uint4*)srcH;
                uint4* d4 = (uint4*)wst;
#pragma unroll
                for (int i = 0; i < 16; ++i) d4[tid + 128 * i] = __ldg(s4 + tid + 128 * i);
            }
            __syncthreads();
#pragma unroll
            for (int ks = 0; ks < 8; ++ks) {
                uint32_t ah0[4], ah1[4], al0[4], al1[4];
                ldmA(ah0, suH, mrow, ks * 16, lane);
                ldmA(ah1, suH, mrow + 16, ks * 16, lane);
                ldmA(al0, suL, mrow, ks * 16, lane);
                ldmA(al1, suL, mrow + 16, ks * 16, lane);
#pragma unroll
                for (int nt = 0; nt < 16; ++nt) {
                    uint2 bb = wst[(ks * 16 + nt) * 32 + lane];
                    mma16816(c[0][nt], ah0, bb);
                    mma16816(c[1][nt], ah1, bb);
                    mma16816(c[0][nt], al0, bb);
                    mma16816(c[1][nt], al1, bb);
                }
            }
            // ---- stage W-lo, run product Ah*Bl ----
            __syncthreads();
            {
                const uint4* s4 = (const uint4*)srcL;
                uint4* d4 = (uint4*)wst;
#pragma unroll
                for (int i = 0; i < 16; ++i) d4[tid + 128 * i] = __ldg(s4 + tid + 128 * i);
            }
            __syncthreads();
#pragma unroll
            for (int ks = 0; ks < 8; ++ks) {
                uint32_t ah0[4], ah1[4];
                ldmA(ah0, suH, mrow, ks * 16, lane);
                ldmA(ah1, suH, mrow + 16, ks * 16, lane);
#pragma unroll
                for (int nt = 0; nt < 16; ++nt) {
                    uint2 bb = wst[(ks * 16 + nt) * 32 + lane];
                    mma16816(c[0][nt], ah0, bb);
                    mma16816(c[1][nt], ah1, bb);
                }
            }
        }

        __syncwarp();  // all reads of act rows by this warp done before overwrite

        if (l < 7) {
            // epilogue: bias + relu + hi/lo split back into act buffers
            const float* bia = sbias + l * 128;
#pragma unroll
            for (int mt = 0; mt < 2; ++mt) {
                const int r0 = mrow + mt * 16 + (lane >> 2);
#pragma unroll
                for (int nt = 0; nt < 16; ++nt) {
                    const int n0 = nt * 8 + (lane & 3) * 2;
                    float v0 = fmaxf(c[mt][nt][0] + bia[n0], 0.f);
                    float v1 = fmaxf(c[mt][nt][1] + bia[n0 + 1], 0.f);
                    float v2 = fmaxf(c[mt][nt][2] + bia[n0], 0.f);
                    float v3 = fmaxf(c[mt][nt][3] + bia[n0 + 1], 0.f);
                    __nv_bfloat16 h0 = __float2bfloat16_rn(v0), h1 = __float2bfloat16_rn(v1);
                    __nv_bfloat16 h2 = __float2bfloat16_rn(v2), h3 = __float2bfloat16_rn(v3);
                    uint32_t pH0 = (uint32_t)__bfloat16_as_ushort(h0) | ((uint32_t)__bfloat16_as_ushort(h1) << 16);
                    uint32_t pH1 = (uint32_t)__bfloat16_as_ushort(h2) | ((uint32_t)__bfloat16_as_ushort(h3) << 16);
                    __nv_bfloat16 l0 = __float2bfloat16_rn(v0 - __bfloat162float(h0));
                    __nv_bfloat16 l1 = __float2bfloat16_rn(v1 - __bfloat162float(h1));
                    __nv_bfloat16 l2 = __float2bfloat16_rn(v2 - __bfloat162float(h2));
                    __nv_bfloat16 l3 = __float2bfloat16_rn(v3 - __bfloat162float(h3));
                    uint32_t pL0 = (uint32_t)__bfloat16_as_ushort(l0) | ((uint32_t)__bfloat16_as_ushort(l1) << 16);
                    uint32_t pL1 = (uint32_t)__bfloat16_as_ushort(l2) | ((uint32_t)__bfloat16_as_ushort(l3) << 16);
                    *(uint32_t*)(actH + r0 * ROWB + n0 * 2) = pH0;
                    *(uint32_t*)(actH + (r0 + 8) * ROWB + n0 * 2) = pH1;
                    *(uint32_t*)(actL + r0 * ROWB + n0 * 2) = pL0;
                    *(uint32_t*)(actL + (r0 + 8) * ROWB + n0 * 2) = pL1;
                }
            }
            __syncwarp();
        } else {
            // final layer: write pre-activation last_feat, accumulate head
            const float* bia = sbias + 7 * 128;
            float* out2 = out + (size_t)NPTS * 3;
            float hs[2][2][3];
#pragma unroll
            for (int mt = 0; mt < 2; ++mt)
#pragma unroll
                for (int rr = 0; rr < 2; ++rr)
#pragma unroll
                    for (int cc = 0; cc < 3; ++cc) hs[mt][rr][cc] = 0.f;
#pragma unroll
            for (int mt = 0; mt < 2; ++mt) {
                const int r0 = mrow + mt * 16 + (lane >> 2);
#pragma unroll
                for (int nt = 0; nt < 16; ++nt) {
                    const int n0 = nt * 8 + (lane & 3) * 2;
                    float pre0 = c[mt][nt][0] + bia[n0];
                    float pre1 = c[mt][nt][1] + bia[n0 + 1];
                    float pre2 = c[mt][nt][2] + bia[n0];
                    float pre3 = c[mt][nt][3] + bia[n0 + 1];
                    *(float2*)(out2 + (size_t)(bp0 + r0) * HID + n0) = make_float2(pre0, pre1);
                    *(float2*)(out2 + (size_t)(bp0 + r0 + 8) * HID + n0) = make_float2(pre2, pre3);
                    float a0 = fmaxf(pre0, 0.f), a1 = fmaxf(pre1, 0.f);
                    float a2 = fmaxf(pre2, 0.f), a3 = fmaxf(pre3, 0.f);
#pragma unroll
                    for (int cc = 0; cc < 3; ++cc) {
                        hs[mt][0][cc] = fmaf(a0, swout[cc * 128 + n0], hs[mt][0][cc]);
                        hs[mt][0][cc] = fmaf(a1, swout[cc * 128 + n0 + 1], hs[mt][0][cc]);
                        hs[mt][1][cc] = fmaf(a2, swout[cc * 128 + n0], hs[mt][1][cc]);
                        hs[mt][1][cc] = fmaf(a3, swout[cc * 128 + n0 + 1], hs[mt][1][cc]);
                    }
                }
            }
            // reduce over the 4 lanes sharing the same rows
#pragma unroll
            for (int mt = 0; mt < 2; ++mt)
#pragma unroll
                for (int rr = 0; rr < 2; ++rr)
#pragma unroll
                    for (int cc = 0; cc < 3; ++cc) {
                        float v = hs[mt][rr][cc];
                        v += __shfl_xor_sync(0xffffffffu, v, 1);
                        v += __shfl_xor_sync(0xffffffffu, v, 2);
                        hs[mt][rr][cc] = v;
                    }
            if ((lane & 3) == 0) {
#pragma unroll
                for (int mt = 0; mt < 2; ++mt)
#pragma unroll
                    for (int rr = 0; rr < 2; ++rr) {
                        const int r = mrow + mt * 16 + (lane >> 2) + rr * 8;
                        const int gp = bp0 + r;
#pragma unroll
                        for (int cc = 0; cc < 3; ++cc)
                            out[gp * 3 + cc] = pts[gp * 3 + cc] + g_gshift[gp * 3 + cc]
                                               + hs[mt][rr][cc] + sbout[cc];
                    }
            }
        }
    }
}

// ---------------------------------------------------------------------------
extern "C" void kernel_launch(void* const* d_in, const int* in_sizes, int n_in,
                              void* d_out, int out_size) {
    const float* pts      = (const float*)d_in[0];
    const float* deformed = (const float*)d_in[1];
    const float* cano     = (const float*)d_in[2];
    const float* latent   = (const float*)d_in[3];
    const float* w[8];
    const float* b[8];
    for (int i = 0; i < 8; ++i) {
        w[i] = (const float*)d_in[4 + 2 * i];
        b[i] = (const float*)d_in[5 + 2 * i];
    }
    const float* w_out = (const float*)d_in[20];
    const float* b_out = (const float*)d_in[21];
    float* out = (float*)d_out;

    const int smem_nn = VV * 16;
    cudaFuncSetAttribute(nn_kernel, cudaFuncAttributeMaxDynamicSharedMemorySize, smem_nn);
    cudaFuncSetAttribute(mlp_mma_kernel, cudaFuncAttributeMaxDynamicSharedMemorySize, SMEM_MLP);

    prep_wfrag<<<288, 256>>>(w[0], w[1], w[2], w[3], w[4], w[5], w[6], w[7]);
    nn_kernel<<<NPTS / 512, 256, smem_nn>>>(pts, deformed, cano);
    mlp_mma_kernel<<<NPTS / 128, 128, SMEM_MLP>>>(pts, latent, b[0], b[1], b[2], b[3], b[4],
                                                  b[5], b[6], b[7], w_out, b_out, out);
}